// round 1
// baseline (speedup 1.0000x reference)
#include <cuda_runtime.h>
#include <cstdint>
#include <cstddef>

// EMA along T for x[B=8, T=8192, C=512] fp32.
// s[0]=x[0]; s[t]=0.99*s[t-1]+0.01*x[t].
// Chunked along T (K=8 chunks of L=1024), each chunk warm-started W=1024 steps
// back with state 0 (truncation error 0.99^1024 ~ 3.4e-5 << 1e-3 tolerance).
// Loads: 6-stage cp.async.bulk -> SMEM pipeline (32KB/stage). Stores: streaming.

#define ALPHA_F 0.01f
#define DECAY_F 0.99f

constexpr int B_ = 8;
constexpr int T_ = 8192;
constexpr int C_ = 512;
constexpr int KCH = 8;               // chunks per (b)-chain
constexpr int LCH = T_ / KCH;        // 1024 output steps per chunk
constexpr int WARM = 1024;           // warmup steps (truncated history)
constexpr int STAGE_T = 16;          // timesteps per pipeline stage
constexpr int STAGE_BYTES = STAGE_T * C_ * 4;   // 32768
constexpr int NSTAGES = 6;                       // 192 KB dynamic smem
constexpr int THREADS = C_ / 2;      // 256 threads, one float2 (2 channels) each

__device__ __forceinline__ uint32_t smem_u32(const void* p) {
    uint32_t a;
    asm("{ .reg .u64 t; cvta.to.shared.u64 t, %1; cvt.u32.u64 %0, t; }"
        : "=r"(a) : "l"(p));
    return a;
}

__device__ __forceinline__ void mbar_init(uint32_t bar, uint32_t cnt) {
    asm volatile("mbarrier.init.shared.b64 [%0], %1;" :: "r"(bar), "r"(cnt) : "memory");
}

__device__ __forceinline__ void mbar_expect_tx(uint32_t bar, uint32_t bytes) {
    asm volatile("mbarrier.arrive.expect_tx.shared.b64 _, [%0], %1;"
                 :: "r"(bar), "r"(bytes) : "memory");
}

__device__ __forceinline__ void bulk_g2s(uint32_t dst, const void* src,
                                         uint32_t bytes, uint32_t bar) {
    asm volatile(
        "cp.async.bulk.shared::cta.global.mbarrier::complete_tx::bytes "
        "[%0], [%1], %2, [%3];"
        :: "r"(dst), "l"(src), "r"(bytes), "r"(bar) : "memory");
}

__device__ __forceinline__ void mbar_wait(uint32_t bar, uint32_t parity) {
    uint32_t done;
    asm volatile(
        "{\n\t.reg .pred p;\n\t"
        "mbarrier.try_wait.parity.acquire.cta.shared::cta.b64 p, [%1], %2;\n\t"
        "selp.b32 %0, 1, 0, p;\n\t}"
        : "=r"(done) : "r"(bar), "r"(parity) : "memory");
    while (!done) {
        asm volatile(
            "{\n\t.reg .pred p;\n\t"
            "mbarrier.try_wait.parity.acquire.cta.shared::cta.b64 p, [%1], %2, 0x989680;\n\t"
            "selp.b32 %0, 1, 0, p;\n\t}"
            : "=r"(done) : "r"(bar), "r"(parity) : "memory");
    }
}

__global__ void __launch_bounds__(THREADS, 1)
ema_scan_kernel(const float* __restrict__ x, float* __restrict__ out)
{
    extern __shared__ __align__(128) unsigned char smem_raw[];
    __shared__ __align__(8) unsigned long long mbar_store[NSTAGES];

    const int tid = threadIdx.x;
    const int b   = blockIdx.x >> 3;          // / KCH
    const int k   = blockIdx.x & (KCH - 1);

    const int t_out0 = k * LCH;                          // first stored timestep
    const int ts     = (k == 0) ? 0 : (t_out0 - WARM);   // first loaded timestep
    const int nsteps = (k == 0) ? LCH : (LCH + WARM);
    const int nstg   = nsteps / STAGE_T;                 // 64 or 128
    const int out_stage0 = (t_out0 - ts) / STAGE_T;      // 0 or 64

    const float* src = x + ((size_t)b * T_ + (size_t)ts) * C_;
    float* dst = out + ((size_t)b * T_ + (size_t)t_out0) * C_ + tid * 2;

    const uint32_t sbase = smem_u32(smem_raw);
    const uint32_t mbase = smem_u32(mbar_store);

    if (tid == 0) {
        #pragma unroll
        for (int s = 0; s < NSTAGES; s++) mbar_init(mbase + s * 8, 1);
    }
    __syncthreads();

    // Prologue: fill the pipeline.
    if (tid == 0) {
        const int pre = (nstg < NSTAGES) ? nstg : NSTAGES;
        for (int s = 0; s < pre; s++) {
            const uint32_t bar = mbase + s * 8;
            mbar_expect_tx(bar, STAGE_BYTES);
            bulk_g2s(sbase + (uint32_t)s * STAGE_BYTES,
                     src + (size_t)s * STAGE_T * C_, STAGE_BYTES, bar);
        }
    }

    float sx = 0.0f, sy = 0.0f;
    const uint32_t lane = (uint32_t)tid * 8u;

    for (int i = 0; i < nstg; i++) {
        const int slot = i % NSTAGES;
        const uint32_t parity = (uint32_t)((i / NSTAGES) & 1);
        mbar_wait(mbase + (uint32_t)slot * 8, parity);

        const uint32_t p = sbase + (uint32_t)slot * STAGE_BYTES + lane;

        if (i >= out_stage0) {
            // Output stage: recurrence + streaming store.
            float* drow = dst + (size_t)(i - out_stage0) * STAGE_T * C_;
            #pragma unroll
            for (int r = 0; r < STAGE_T; r++) {
                float2 xv;
                asm volatile("ld.shared.v2.f32 {%0,%1}, [%2];"
                             : "=f"(xv.x), "=f"(xv.y) : "r"(p + r * (C_ * 4)));
                sx = fmaf(sx, DECAY_F, ALPHA_F * xv.x);
                sy = fmaf(sy, DECAY_F, ALPHA_F * xv.y);
                if (r == 0 && i == 0 && k == 0) {
                    // Global t=0 has weight 1.0, not alpha: fix up 0.01*x -> x.
                    sx *= 100.0f; sy *= 100.0f;
                }
                __stcs(reinterpret_cast<float2*>(drow + (size_t)r * C_),
                       make_float2(sx, sy));
            }
        } else {
            // Warmup stage: recurrence only, no stores.
            #pragma unroll
            for (int r = 0; r < STAGE_T; r++) {
                float2 xv;
                asm volatile("ld.shared.v2.f32 {%0,%1}, [%2];"
                             : "=f"(xv.x), "=f"(xv.y) : "r"(p + r * (C_ * 4)));
                sx = fmaf(sx, DECAY_F, ALPHA_F * xv.x);
                sy = fmaf(sy, DECAY_F, ALPHA_F * xv.y);
            }
        }

        __syncthreads();   // all consumers done with this slot

        if (tid == 0) {
            const int ns = i + NSTAGES;
            if (ns < nstg) {
                const uint32_t bar = mbase + (uint32_t)slot * 8;
                mbar_expect_tx(bar, STAGE_BYTES);
                bulk_g2s(sbase + (uint32_t)slot * STAGE_BYTES,
                         src + (size_t)ns * STAGE_T * C_, STAGE_BYTES, bar);
            }
        }
    }
}

extern "C" void kernel_launch(void* const* d_in, const int* in_sizes, int n_in,
                              void* d_out, int out_size)
{
    const float* x = (const float*)d_in[0];
    float* out = (float*)d_out;
    (void)in_sizes; (void)n_in; (void)out_size;

    cudaFuncSetAttribute(ema_scan_kernel,
                         cudaFuncAttributeMaxDynamicSharedMemorySize,
                         NSTAGES * STAGE_BYTES);
    ema_scan_kernel<<<B_ * KCH, THREADS, NSTAGES * STAGE_BYTES>>>(x, out);
}

// round 2
// speedup vs baseline: 1.1597x; 1.1597x over previous
#include <cuda_runtime.h>
#include <cstdint>
#include <cstddef>

// EMA along T for x[B=8, T=8192, C=512] fp32.
//   out[0]=x[0]; out[t]=0.99*out[t-1]+0.01*x[t]
// Channel-split: 64 blocks, each owns (b, 64-channel slice) and scans the full
// T=8192 serially -> zero redundant DRAM traffic (268 MB total, the floor).
// Rescaled recurrence z=100*s: z_t = fma(z, 0.99, x_t); out = 0.01*z  (1 FFMA chain).
// Loads: cp.async.cg 16B -> 12-stage x 16KB smem pipeline. Stores: streaming STG.

constexpr int B_ = 8;
constexpr int T_ = 8192;
constexpr int C_ = 512;

constexpr int SLICE_C   = 64;                 // channels per block
constexpr int SLICES    = C_ / SLICE_C;       // 8
constexpr int THREADS   = SLICE_C;            // 64 threads, 1 channel each
constexpr int RPS       = 64;                 // rows (timesteps) per stage
constexpr int STAGE_B   = RPS * SLICE_C * 4;  // 16384 bytes
constexpr int NSTG      = 12;                 // 192 KB dynamic smem
constexpr int NUM_STG   = T_ / RPS;           // 128 stages
constexpr int CHUNKS    = STAGE_B / 16;       // 1024 x 16B per stage
constexpr int CPT       = CHUNKS / THREADS;   // 16 cp.asyncs per thread per stage

__device__ __forceinline__ uint32_t smem_u32(const void* p) {
    uint32_t a;
    asm("{ .reg .u64 t; cvta.to.shared.u64 t, %1; cvt.u32.u64 %0, t; }"
        : "=r"(a) : "l"(p));
    return a;
}

__device__ __forceinline__ void cp_async16(uint32_t sdst, const void* gsrc) {
    asm volatile("cp.async.cg.shared.global [%0], [%1], 16;"
                 :: "r"(sdst), "l"(gsrc) : "memory");
}

__device__ __forceinline__ void cp_commit() {
    asm volatile("cp.async.commit_group;" ::: "memory");
}

template <int N>
__device__ __forceinline__ void cp_wait() {
    asm volatile("cp.async.wait_group %0;" :: "n"(N) : "memory");
}

__global__ void __launch_bounds__(THREADS, 1)
ema_cs_kernel(const float* __restrict__ x, float* __restrict__ out)
{
    extern __shared__ __align__(128) unsigned char smem_raw[];

    const int tid   = threadIdx.x;
    const int b     = blockIdx.x >> 3;            // / SLICES
    const int slice = blockIdx.x & (SLICES - 1);

    const uint32_t sbase = smem_u32(smem_raw);

    // Base pointers for this (b, slice).
    const float* xin = x   + (size_t)b * T_ * C_ + slice * SLICE_C;
    float*       dst = out + (size_t)b * T_ * C_ + slice * SLICE_C + tid;

    // cp.async addressing: chunk q in [0,1024): row = q>>4, 16B segment = q&15.
    // Thread t issues q = j*64 + t for j in [0,16): 16 consecutive threads cover
    // one contiguous 256B row slice -> fully coalesced.
    auto issue_stage = [&](int stage, int slot) {
        const float* g0 = xin + (size_t)stage * RPS * C_;
        const uint32_t s0 = sbase + (uint32_t)slot * STAGE_B;
        #pragma unroll
        for (int j = 0; j < CPT; j++) {
            const int q   = j * THREADS + tid;
            const int row = q >> 4;
            const int seg = q & 15;
            cp_async16(s0 + (uint32_t)q * 16,
                       g0 + (size_t)row * C_ + seg * 4);
        }
    };

    // Prologue: fill NSTG-1 = 11 stages, one group each.
    #pragma unroll
    for (int s = 0; s < NSTG - 1; s++) {
        issue_stage(s, s);
        cp_commit();
    }

    float z = 0.0f;   // z = 100 * EMA state

    for (int i = 0; i < NUM_STG; i++) {
        const int slot = i % NSTG;

        cp_wait<NSTG - 2>();   // stage i complete (11 groups always pending)
        __syncthreads();       // make all threads' copies visible; slot (i-1)%NSTG free

        // Refill the freed slot (stage i + NSTG-1). Always commit (empty group
        // keeps the pending-group count constant so cp_wait<10> stays correct).
        const int ns = i + NSTG - 1;
        if (ns < NUM_STG) issue_stage(ns, ns % NSTG);
        cp_commit();

        // Consume: 64 timesteps of the recurrence for this thread's channel.
        const uint32_t p = sbase + (uint32_t)slot * STAGE_B + (uint32_t)tid * 4;
        float* drow = dst + (size_t)i * RPS * C_;

        if (i == 0) {
            // First stage: t=0 has weight 1.0 (out[0] = x[0]) -> z0 = 100*x0.
            #pragma unroll
            for (int r = 0; r < RPS; r++) {
                float xv;
                asm volatile("ld.shared.f32 %0, [%1];"
                             : "=f"(xv) : "r"(p + r * (SLICE_C * 4)));
                z = fmaf(z, 0.99f, xv);
                if (r == 0) z *= 100.0f;
                __stcs(drow + (size_t)r * C_, 0.01f * z);
            }
        } else {
            #pragma unroll
            for (int r = 0; r < RPS; r++) {
                float xv;
                asm volatile("ld.shared.f32 %0, [%1];"
                             : "=f"(xv) : "r"(p + r * (SLICE_C * 4)));
                z = fmaf(z, 0.99f, xv);
                __stcs(drow + (size_t)r * C_, 0.01f * z);
            }
        }
    }
}

extern "C" void kernel_launch(void* const* d_in, const int* in_sizes, int n_in,
                              void* d_out, int out_size)
{
    const float* x = (const float*)d_in[0];
    float* out = (float*)d_out;
    (void)in_sizes; (void)n_in; (void)out_size;

    cudaFuncSetAttribute(ema_cs_kernel,
                         cudaFuncAttributeMaxDynamicSharedMemorySize,
                         NSTG * STAGE_B);
    ema_cs_kernel<<<B_ * SLICES, THREADS, NSTG * STAGE_B>>>(x, out);
}